// round 10
// baseline (speedup 1.0000x reference)
#include <cuda_runtime.h>
#include <math.h>

#define T_DIM 16
#define B_DIM 512
#define E_DIM 256
#define V_DIM 25
#define NPAIR (T_DIM * B_DIM * V_DIM)   // 204800 (t,b,v) sites
#define RED_BLOCKS 256

// Scratch (no allocations allowed).
__device__ double d_part[RED_BLOCKS][5];
__device__ float4 d_A[E_DIM];           // {w0, w1, mean, rstd}  (R1-exact coefs)
__device__ float2 d_G[E_DIM];           // {gamma, beta}
__device__ unsigned int d_cnt = 0;      // last-block ticket; self-resets each call

// ---------------------------------------------------------------------------
// Kernel 1: UNCHANGED from the passing R8 kernel (numerics frozen).
// ---------------------------------------------------------------------------
__global__ void moments_and_coefs(const float* __restrict__ x,
                                  const float* __restrict__ W,
                                  const float* __restrict__ gamma,
                                  const float* __restrict__ beta) {
    float f0 = 0.f, f1 = 0.f, f2 = 0.f, f3 = 0.f, f4 = 0.f;
    int stride = gridDim.x * blockDim.x;
    for (int j = blockIdx.x * blockDim.x + threadIdx.x; j < NPAIR; j += stride) {
        int tb = j / V_DIM;
        int v  = j - tb * V_DIM;
        const float* base = x + tb * (2 * V_DIM);
        float x0 = base[v];
        float x1 = base[V_DIM + v];
        f0 += x0;
        f1 += x1;
        f2 = fmaf(x0, x0, f2);
        f3 = fmaf(x1, x1, f3);
        f4 = fmaf(x0, x1, f4);
    }
    double s0 = f0, s1 = f1, s2 = f2, s3 = f3, s4 = f4;
    #pragma unroll
    for (int o = 16; o > 0; o >>= 1) {
        s0 += __shfl_down_sync(0xffffffffu, s0, o);
        s1 += __shfl_down_sync(0xffffffffu, s1, o);
        s2 += __shfl_down_sync(0xffffffffu, s2, o);
        s3 += __shfl_down_sync(0xffffffffu, s3, o);
        s4 += __shfl_down_sync(0xffffffffu, s4, o);
    }
    __shared__ double sh[8][5];
    int w = threadIdx.x >> 5, l = threadIdx.x & 31;
    if (l == 0) { sh[w][0] = s0; sh[w][1] = s1; sh[w][2] = s2; sh[w][3] = s3; sh[w][4] = s4; }
    __syncthreads();
    if (threadIdx.x == 0) {
        double t0 = 0.0, t1 = 0.0, t2 = 0.0, t3 = 0.0, t4 = 0.0;
        #pragma unroll
        for (int i = 0; i < 8; i++) {
            t0 += sh[i][0]; t1 += sh[i][1]; t2 += sh[i][2]; t3 += sh[i][3]; t4 += sh[i][4];
        }
        d_part[blockIdx.x][0] = t0;
        d_part[blockIdx.x][1] = t1;
        d_part[blockIdx.x][2] = t2;
        d_part[blockIdx.x][3] = t3;
        d_part[blockIdx.x][4] = t4;
        __threadfence();
    }

    __shared__ bool isLast;
    if (threadIdx.x == 0) {
        unsigned int t = atomicAdd(&d_cnt, 1u);
        isLast = (t == (unsigned int)(RED_BLOCKS - 1));
    }
    __syncthreads();
    if (!isLast) return;

    double p0 = d_part[threadIdx.x][0];
    double p1 = d_part[threadIdx.x][1];
    double p2 = d_part[threadIdx.x][2];
    double p3 = d_part[threadIdx.x][3];
    double p4 = d_part[threadIdx.x][4];
    #pragma unroll
    for (int o = 16; o > 0; o >>= 1) {
        p0 += __shfl_down_sync(0xffffffffu, p0, o);
        p1 += __shfl_down_sync(0xffffffffu, p1, o);
        p2 += __shfl_down_sync(0xffffffffu, p2, o);
        p3 += __shfl_down_sync(0xffffffffu, p3, o);
        p4 += __shfl_down_sync(0xffffffffu, p4, o);
    }
    __shared__ double dsh[8][5];
    if (l == 0) { dsh[w][0] = p0; dsh[w][1] = p1; dsh[w][2] = p2; dsh[w][3] = p3; dsh[w][4] = p4; }
    __syncthreads();
    __shared__ double tot[5];
    if (threadIdx.x < 5) {
        double t = 0.0;
        #pragma unroll
        for (int i = 0; i < 8; i++) t += dsh[i][threadIdx.x];
        tot[threadIdx.x] = t;
    }
    __syncthreads();

    const double invN = 1.0 / (double)NPAIR;
    double m0  = tot[0] * invN;
    double m1  = tot[1] * invN;
    double s00 = tot[2] * invN;
    double s11 = tot[3] * invN;
    double s01 = tot[4] * invN;

    int e = threadIdx.x;
    float w0 = W[2 * e];
    float w1 = W[2 * e + 1];
    double mean = (double)w0 * m0 + (double)w1 * m1;
    double ey2  = (double)w0 * (double)w0 * s00
                + 2.0 * (double)w0 * (double)w1 * s01
                + (double)w1 * (double)w1 * s11;
    double var = ey2 - mean * mean;
    if (var < 0.0) var = 0.0;
    float rstd = (float)(1.0 / sqrt(var + 1e-5));
    d_A[e] = make_float4(w0, w1, (float)mean, rstd);
    d_G[e] = make_float2(gamma[e], beta[e]);

    if (threadIdx.x == 0) d_cnt = 0;  // reset for next graph replay
}

// ---------------------------------------------------------------------------
// Kernel 2: fused conv1x1 + BN + LIF scan.
// Block = (b, e-half of 128 channels): grid 1024 x 160 threads, 8 blocks/SM
// -> single balanced wave (imbalance ~1.01 vs 1.16 at 512x320).
// x staged as TWO parity-shifted float4 tables so each quad reads its four
// (x0,x1) pairs with 2 aligned LDS.128 instead of 4 LDS.64:
//   xsA4[t][j] = {x0[2j],   x1[2j],   x0[2j+1], x1[2j+1]}   (pairs at even v)
//   xsB4[t][j] = {x0[2j+1], x1[2j+1], x0[2j+2], x1[2j+2]}   (pairs at odd v)
// both indices taken mod 25 (x repeats across channels), so wrap quads work.
// Per-element arithmetic IDENTICAL to the passing kernel -> bit-same output.
// ---------------------------------------------------------------------------
#define EH 128                 // channels per block (half of E)
#define QH (EH * V_DIM / 4)    // 800 quads per block
#define NTH 160                // threads per block (5 quads each)

__global__ void __launch_bounds__(NTH, 8)
lif_main(const float* __restrict__ x, float* __restrict__ out) {
    __shared__ float2 xs2[T_DIM * V_DIM];     // raw staging [t][v]
    __shared__ float4 xsA4[T_DIM * 13];       // even-parity pairs, 13 per t
    __shared__ float4 xsB4[T_DIM * 13];       // odd-parity pairs, 13 per t
    __shared__ float4 As[EH];
    __shared__ float2 Gs[EH];

    int b    = blockIdx.x >> 1;
    int half = blockIdx.x & 1;
    int tid  = threadIdx.x;

    // phase 1: raw x slice for this b
    for (int i = tid; i < T_DIM * V_DIM; i += NTH) {
        int t = i / V_DIM, v = i - t * V_DIM;
        const float* base = x + (t * B_DIM + b) * (2 * V_DIM);
        xs2[i] = make_float2(base[v], base[V_DIM + v]);
    }
    // coefs for this half
    if (tid < EH) {
        As[tid] = d_A[half * EH + tid];
        Gs[tid] = d_G[half * EH + tid];
    }
    __syncthreads();

    // phase 2: build parity tables (values copied verbatim; mod-25 wrap)
    for (int i = tid; i < T_DIM * 13; i += NTH) {
        int t = i / 13, j = i - t * 13;
        int vA0 = 2 * j;                       // 0..24
        int vA1 = (2 * j + 1) % V_DIM;
        int vB0 = (2 * j + 1) % V_DIM;
        int vB1 = (2 * j + 2) % V_DIM;
        float2 a0 = xs2[t * V_DIM + vA0];
        float2 a1 = xs2[t * V_DIM + vA1];
        float2 b0 = xs2[t * V_DIM + vB0];
        float2 b1 = xs2[t * V_DIM + vB1];
        xsA4[i] = make_float4(a0.x, a0.y, a1.x, a1.y);
        xsB4[i] = make_float4(b0.x, b0.y, b1.x, b1.y);
    }
    __syncthreads();

    float4* o4 = reinterpret_cast<float4*>(out);

    #pragma unroll 1
    for (int k = 0; k < 5; k++) {
        int q  = tid + k * NTH;               // local quad in [0,800)
        int p0 = 4 * q;                       // local position in [0,3200)
        // per-element coefs (same mapping/order as the passing kernel)
        float w0[4], w1[4], mn[4], rs[4], ga[4], be[4];
        #pragma unroll
        for (int i = 0; i < 4; i++) {
            int pp = p0 + i;
            int e  = pp / V_DIM;              // local channel 0..127
            float4 A = As[e];
            float2 G = Gs[e];
            w0[i] = A.x; w1[i] = A.y; mn[i] = A.z; rs[i] = A.w;
            ga[i] = G.x; be[i] = G.y;
        }
        // pair pointers: pair0 covers elements 0,1 ; pair1 covers 2,3
        int vA = p0 % V_DIM;
        int vB = (p0 + 2) % V_DIM;
        const float4* pA = ((vA & 1) ? xsB4 : xsA4) + (vA >> 1);
        const float4* pB = ((vB & 1) ? xsB4 : xsA4) + (vB >> 1);

        float vs[4] = {0.f, 0.f, 0.f, 0.f};
        float4* op = o4 + b * (E_DIM * V_DIM / 4) + half * QH + q;
        #pragma unroll
        for (int t = 0; t < T_DIM; t++) {
            float4 xa = pA[t * 13];
            float4 xb = pB[t * 13];
            float x0v[4] = {xa.x, xa.z, xb.x, xb.z};
            float x1v[4] = {xa.y, xa.w, xb.y, xb.w};
            float4 sp4;
            float* spp = reinterpret_cast<float*>(&sp4);
            #pragma unroll
            for (int i = 0; i < 4; i++) {
                float y  = fmaf(x0v[i], w0[i], x1v[i] * w1[i]); // conv1x1 (K=2)
                float z  = (y - mn[i]) * rs[i];                 // BN normalize
                float yn = fmaf(z, ga[i], be[i]);               // gamma/beta
                float vn = fmaf(yn - vs[i], 0.5f, vs[i]);       // v += (yn-v)/tau
                float sp = (vn >= 1.0f) ? 1.0f : 0.0f;          // threshold
                vs[i] = vn * (1.0f - sp);                       // hard reset
                spp[i] = sp;
            }
            __stcs(op, sp4);                  // streaming store (write-once)
            op += B_DIM * E_DIM * V_DIM / 4;
        }
    }
}

// ---------------------------------------------------------------------------
extern "C" void kernel_launch(void* const* d_in, const int* in_sizes, int n_in,
                              void* d_out, int out_size) {
    const float* x     = (const float*)d_in[0];
    const float* W     = (const float*)d_in[1];
    const float* gamma = (const float*)d_in[2];
    const float* beta  = (const float*)d_in[3];
    float* out = (float*)d_out;

    moments_and_coefs<<<RED_BLOCKS, 256>>>(x, W, gamma, beta);
    lif_main<<<B_DIM * 2, NTH>>>(x, out);
}

// round 11
// speedup vs baseline: 1.0303x; 1.0303x over previous
#include <cuda_runtime.h>
#include <math.h>

#define T_DIM 16
#define B_DIM 512
#define E_DIM 256
#define V_DIM 25
#define NPAIR (T_DIM * B_DIM * V_DIM)   // 204800 (t,b,v) sites
#define RED_BLOCKS 256

// Scratch (no allocations allowed).
__device__ double d_part[RED_BLOCKS][5];
__device__ float4 d_A[E_DIM];           // {w0, w1, mean, rstd}  (R1-exact coefs)
__device__ float2 d_G[E_DIM];           // {gamma, beta}
__device__ unsigned int d_cnt = 0;      // last-block ticket; self-resets each call

// ---------------------------------------------------------------------------
// Kernel 1: UNCHANGED from the passing R8/R10 kernel (numerics frozen).
// ---------------------------------------------------------------------------
__global__ void moments_and_coefs(const float* __restrict__ x,
                                  const float* __restrict__ W,
                                  const float* __restrict__ gamma,
                                  const float* __restrict__ beta) {
    float f0 = 0.f, f1 = 0.f, f2 = 0.f, f3 = 0.f, f4 = 0.f;
    int stride = gridDim.x * blockDim.x;
    for (int j = blockIdx.x * blockDim.x + threadIdx.x; j < NPAIR; j += stride) {
        int tb = j / V_DIM;
        int v  = j - tb * V_DIM;
        const float* base = x + tb * (2 * V_DIM);
        float x0 = base[v];
        float x1 = base[V_DIM + v];
        f0 += x0;
        f1 += x1;
        f2 = fmaf(x0, x0, f2);
        f3 = fmaf(x1, x1, f3);
        f4 = fmaf(x0, x1, f4);
    }
    double s0 = f0, s1 = f1, s2 = f2, s3 = f3, s4 = f4;
    #pragma unroll
    for (int o = 16; o > 0; o >>= 1) {
        s0 += __shfl_down_sync(0xffffffffu, s0, o);
        s1 += __shfl_down_sync(0xffffffffu, s1, o);
        s2 += __shfl_down_sync(0xffffffffu, s2, o);
        s3 += __shfl_down_sync(0xffffffffu, s3, o);
        s4 += __shfl_down_sync(0xffffffffu, s4, o);
    }
    __shared__ double sh[8][5];
    int w = threadIdx.x >> 5, l = threadIdx.x & 31;
    if (l == 0) { sh[w][0] = s0; sh[w][1] = s1; sh[w][2] = s2; sh[w][3] = s3; sh[w][4] = s4; }
    __syncthreads();
    if (threadIdx.x == 0) {
        double t0 = 0.0, t1 = 0.0, t2 = 0.0, t3 = 0.0, t4 = 0.0;
        #pragma unroll
        for (int i = 0; i < 8; i++) {
            t0 += sh[i][0]; t1 += sh[i][1]; t2 += sh[i][2]; t3 += sh[i][3]; t4 += sh[i][4];
        }
        d_part[blockIdx.x][0] = t0;
        d_part[blockIdx.x][1] = t1;
        d_part[blockIdx.x][2] = t2;
        d_part[blockIdx.x][3] = t3;
        d_part[blockIdx.x][4] = t4;
        __threadfence();
    }

    __shared__ bool isLast;
    if (threadIdx.x == 0) {
        unsigned int t = atomicAdd(&d_cnt, 1u);
        isLast = (t == (unsigned int)(RED_BLOCKS - 1));
    }
    __syncthreads();
    if (!isLast) return;

    double p0 = d_part[threadIdx.x][0];
    double p1 = d_part[threadIdx.x][1];
    double p2 = d_part[threadIdx.x][2];
    double p3 = d_part[threadIdx.x][3];
    double p4 = d_part[threadIdx.x][4];
    #pragma unroll
    for (int o = 16; o > 0; o >>= 1) {
        p0 += __shfl_down_sync(0xffffffffu, p0, o);
        p1 += __shfl_down_sync(0xffffffffu, p1, o);
        p2 += __shfl_down_sync(0xffffffffu, p2, o);
        p3 += __shfl_down_sync(0xffffffffu, p3, o);
        p4 += __shfl_down_sync(0xffffffffu, p4, o);
    }
    __shared__ double dsh[8][5];
    if (l == 0) { dsh[w][0] = p0; dsh[w][1] = p1; dsh[w][2] = p2; dsh[w][3] = p3; dsh[w][4] = p4; }
    __syncthreads();
    __shared__ double tot[5];
    if (threadIdx.x < 5) {
        double t = 0.0;
        #pragma unroll
        for (int i = 0; i < 8; i++) t += dsh[i][threadIdx.x];
        tot[threadIdx.x] = t;
    }
    __syncthreads();

    const double invN = 1.0 / (double)NPAIR;
    double m0  = tot[0] * invN;
    double m1  = tot[1] * invN;
    double s00 = tot[2] * invN;
    double s11 = tot[3] * invN;
    double s01 = tot[4] * invN;

    int e = threadIdx.x;
    float w0 = W[2 * e];
    float w1 = W[2 * e + 1];
    double mean = (double)w0 * m0 + (double)w1 * m1;
    double ey2  = (double)w0 * (double)w0 * s00
                + 2.0 * (double)w0 * (double)w1 * s01
                + (double)w1 * (double)w1 * s11;
    double var = ey2 - mean * mean;
    if (var < 0.0) var = 0.0;
    float rstd = (float)(1.0 / sqrt(var + 1e-5));
    d_A[e] = make_float4(w0, w1, (float)mean, rstd);
    d_G[e] = make_float2(gamma[e], beta[e]);

    if (threadIdx.x == 0) d_cnt = 0;  // reset for next graph replay
}

// ---------------------------------------------------------------------------
// Kernel 2: fused conv1x1 + BN + LIF scan.
// Grid shape as R10 (1024 blocks x 160 threads, block = (b, 128-channel half)),
// but x staged as TWO SCALAR float arrays xs0[t][v], xs1[t][v]:
//   4B elements, v in [0,25) -> bank v, all distinct -> CONFLICT-FREE LDS.32,
//   lanes sharing a v broadcast for free. Iter cost 8x1 + 12 = 20 LSU cyc
//   vs 28 for the conflicted float2/float4 layouts.
// Per-element arithmetic IDENTICAL to the passing kernel -> bit-same output.
// ---------------------------------------------------------------------------
#define EH 128                 // channels per block (half of E)
#define QH (EH * V_DIM / 4)    // 800 quads per block
#define NTH 160                // threads per block (5 quads each)

__global__ void __launch_bounds__(NTH, 8)
lif_main(const float* __restrict__ x, float* __restrict__ out) {
    __shared__ float xsS[2 * T_DIM * V_DIM];  // [0:400)=x0[t][v], [400:800)=x1[t][v]
    __shared__ float4 As[EH];
    __shared__ float2 Gs[EH];

    int b    = blockIdx.x >> 1;
    int half = blockIdx.x & 1;
    int tid  = threadIdx.x;

    // stage x: 400 (t,v) sites -> two scalar tables
    for (int i = tid; i < T_DIM * V_DIM; i += NTH) {
        int t = i / V_DIM, v = i - t * V_DIM;
        const float* base = x + (t * B_DIM + b) * (2 * V_DIM);
        xsS[i]                 = base[v];          // x0
        xsS[T_DIM * V_DIM + i] = base[V_DIM + v];  // x1
    }
    if (tid < EH) {
        As[tid] = d_A[half * EH + tid];
        Gs[tid] = d_G[half * EH + tid];
    }
    __syncthreads();

    float4* o4 = reinterpret_cast<float4*>(out);

    #pragma unroll 1
    for (int k = 0; k < 5; k++) {
        int q  = tid + k * NTH;               // local quad in [0,800)
        int p0 = 4 * q;                       // local position in [0,3200)
        int vi[4];
        float w0[4], w1[4], mn[4], rs[4], ga[4], be[4];
        #pragma unroll
        for (int i = 0; i < 4; i++) {
            int pp = p0 + i;
            int e  = pp / V_DIM;              // local channel 0..127
            vi[i]  = pp - e * V_DIM;          // v in [0,25)
            float4 A = As[e];
            float2 G = Gs[e];
            w0[i] = A.x; w1[i] = A.y; mn[i] = A.z; rs[i] = A.w;
            ga[i] = G.x; be[i] = G.y;
        }
        float vs[4] = {0.f, 0.f, 0.f, 0.f};
        float4* op = o4 + b * (E_DIM * V_DIM / 4) + half * QH + q;
        #pragma unroll
        for (int t = 0; t < T_DIM; t++) {
            float4 sp4;
            float* spp = reinterpret_cast<float*>(&sp4);
            #pragma unroll
            for (int i = 0; i < 4; i++) {
                // conflict-free scalar LDS; t*V_DIM folds into the immediate
                float x0v = xsS[t * V_DIM + vi[i]];
                float x1v = xsS[T_DIM * V_DIM + t * V_DIM + vi[i]];
                float y  = fmaf(x0v, w0[i], x1v * w1[i]);   // conv1x1 (K=2)
                float z  = (y - mn[i]) * rs[i];             // BN normalize
                float yn = fmaf(z, ga[i], be[i]);           // gamma/beta
                float vn = fmaf(yn - vs[i], 0.5f, vs[i]);   // v += (yn - v)/tau
                float sp = (vn >= 1.0f) ? 1.0f : 0.0f;      // threshold
                vs[i] = vn * (1.0f - sp);                   // hard reset
                spp[i] = sp;
            }
            __stcs(op, sp4);                  // streaming store (write-once)
            op += B_DIM * E_DIM * V_DIM / 4;
        }
    }
}

// ---------------------------------------------------------------------------
extern "C" void kernel_launch(void* const* d_in, const int* in_sizes, int n_in,
                              void* d_out, int out_size) {
    const float* x     = (const float*)d_in[0];
    const float* W     = (const float*)d_in[1];
    const float* gamma = (const float*)d_in[2];
    const float* beta  = (const float*)d_in[3];
    float* out = (float*)d_out;

    moments_and_coefs<<<RED_BLOCKS, 256>>>(x, W, gamma, beta);
    lif_main<<<B_DIM * 2, NTH>>>(x, out);
}

// round 12
// speedup vs baseline: 1.0751x; 1.0435x over previous
#include <cuda_runtime.h>
#include <math.h>

#define T_DIM 16
#define B_DIM 512
#define E_DIM 256
#define V_DIM 25
#define NPAIR (T_DIM * B_DIM * V_DIM)   // 204800 (t,b,v) sites
#define MROWS (T_DIM * B_DIM)           // 8192 rows of 50 floats
#define MBLOCKS 128
#define MTHREADS 64

// Scratch (no allocations allowed).
__device__ double d_part[MBLOCKS][5];
__device__ float4 d_A[E_DIM];           // {w0, w1, mean, rstd}
__device__ float2 d_G[E_DIM];           // {gamma, beta}
__device__ unsigned int d_cnt = 0;      // last-block ticket; self-resets each call

// ---------------------------------------------------------------------------
// Kernel 1 (v2): one thread per (t,b) row (50 contiguous floats, 8B-aligned).
// 25 LDG.64 per thread (MLP=25 -> DRAM latency hidden), fp32 moments in fixed
// v-order, then double for ALL reduction levels. Last-finishing block combines
// and emits per-channel {w0,w1,mean,rstd}+{gamma,beta} (coef math unchanged).
// ---------------------------------------------------------------------------
__global__ void moments_and_coefs(const float* __restrict__ x,
                                  const float* __restrict__ W,
                                  const float* __restrict__ gamma,
                                  const float* __restrict__ beta) {
    int r = blockIdx.x * MTHREADS + threadIdx.x;   // row id in [0, 8192)
    const float2* row2 = reinterpret_cast<const float2*>(x + r * (2 * V_DIM));

    float f[2 * V_DIM];
    #pragma unroll
    for (int j = 0; j < V_DIM; j++) {              // 25 independent LDG.64
        float2 p = row2[j];
        f[2 * j]     = p.x;
        f[2 * j + 1] = p.y;
    }

    float f0 = 0.f, f1 = 0.f, f2 = 0.f, f3 = 0.f, f4 = 0.f;
    #pragma unroll
    for (int v = 0; v < V_DIM; v++) {
        float x0 = f[v];
        float x1 = f[V_DIM + v];
        f0 += x0;
        f1 += x1;
        f2 = fmaf(x0, x0, f2);
        f3 = fmaf(x1, x1, f3);
        f4 = fmaf(x0, x1, f4);
    }

    // promote to double for every reduction level
    double s0 = f0, s1 = f1, s2 = f2, s3 = f3, s4 = f4;
    #pragma unroll
    for (int o = 16; o > 0; o >>= 1) {
        s0 += __shfl_down_sync(0xffffffffu, s0, o);
        s1 += __shfl_down_sync(0xffffffffu, s1, o);
        s2 += __shfl_down_sync(0xffffffffu, s2, o);
        s3 += __shfl_down_sync(0xffffffffu, s3, o);
        s4 += __shfl_down_sync(0xffffffffu, s4, o);
    }
    __shared__ double sh[2][5];
    int w = threadIdx.x >> 5, l = threadIdx.x & 31;
    if (l == 0) { sh[w][0] = s0; sh[w][1] = s1; sh[w][2] = s2; sh[w][3] = s3; sh[w][4] = s4; }
    __syncthreads();
    if (threadIdx.x == 0) {
        d_part[blockIdx.x][0] = sh[0][0] + sh[1][0];
        d_part[blockIdx.x][1] = sh[0][1] + sh[1][1];
        d_part[blockIdx.x][2] = sh[0][2] + sh[1][2];
        d_part[blockIdx.x][3] = sh[0][3] + sh[1][3];
        d_part[blockIdx.x][4] = sh[0][4] + sh[1][4];
        __threadfence();
    }

    // last-block-done: combine partials + compute coefs
    __shared__ bool isLast;
    if (threadIdx.x == 0) {
        unsigned int t = atomicAdd(&d_cnt, 1u);
        isLast = (t == (unsigned int)(MBLOCKS - 1));
    }
    __syncthreads();
    if (!isLast) return;

    // 64 threads: thread i sums partials i and i+64, then tree-reduce
    double p0 = d_part[threadIdx.x][0] + d_part[threadIdx.x + 64][0];
    double p1 = d_part[threadIdx.x][1] + d_part[threadIdx.x + 64][1];
    double p2 = d_part[threadIdx.x][2] + d_part[threadIdx.x + 64][2];
    double p3 = d_part[threadIdx.x][3] + d_part[threadIdx.x + 64][3];
    double p4 = d_part[threadIdx.x][4] + d_part[threadIdx.x + 64][4];
    #pragma unroll
    for (int o = 16; o > 0; o >>= 1) {
        p0 += __shfl_down_sync(0xffffffffu, p0, o);
        p1 += __shfl_down_sync(0xffffffffu, p1, o);
        p2 += __shfl_down_sync(0xffffffffu, p2, o);
        p3 += __shfl_down_sync(0xffffffffu, p3, o);
        p4 += __shfl_down_sync(0xffffffffu, p4, o);
    }
    __shared__ double dsh[2][5];
    if (l == 0) { dsh[w][0] = p0; dsh[w][1] = p1; dsh[w][2] = p2; dsh[w][3] = p3; dsh[w][4] = p4; }
    __syncthreads();
    __shared__ double tot[5];
    if (threadIdx.x < 5) tot[threadIdx.x] = dsh[0][threadIdx.x] + dsh[1][threadIdx.x];
    __syncthreads();

    const double invN = 1.0 / (double)NPAIR;
    double m0  = tot[0] * invN;
    double m1  = tot[1] * invN;
    double s00 = tot[2] * invN;
    double s11 = tot[3] * invN;
    double s01 = tot[4] * invN;

    for (int e = threadIdx.x; e < E_DIM; e += MTHREADS) {
        float w0 = W[2 * e];
        float w1 = W[2 * e + 1];
        double mean = (double)w0 * m0 + (double)w1 * m1;
        double ey2  = (double)w0 * (double)w0 * s00
                    + 2.0 * (double)w0 * (double)w1 * s01
                    + (double)w1 * (double)w1 * s11;
        double var = ey2 - mean * mean;
        if (var < 0.0) var = 0.0;
        float rstd = (float)(1.0 / sqrt(var + 1e-5));
        d_A[e] = make_float4(w0, w1, (float)mean, rstd);
        d_G[e] = make_float2(gamma[e], beta[e]);
    }

    if (threadIdx.x == 0) d_cnt = 0;  // reset for next graph replay
}

// ---------------------------------------------------------------------------
// Kernel 2: fused conv1x1 + BN + LIF scan. Same tiling as the passing R11
// kernel (1024 blocks x 160 threads, conflict-free scalar x tables).
// ONLY change: hard-reset via selects -- bit-identical to vn*(1-sp) since
// sp is exactly 0.0 or 1.0 and vn is finite. Saves 2 FP ops per element.
// ---------------------------------------------------------------------------
#define EH 128                 // channels per block (half of E)
#define QH (EH * V_DIM / 4)    // 800 quads per block
#define NTH 160                // threads per block (5 quads each)

__global__ void __launch_bounds__(NTH, 8)
lif_main(const float* __restrict__ x, float* __restrict__ out) {
    __shared__ float xsS[2 * T_DIM * V_DIM];  // [0:400)=x0[t][v], [400:800)=x1[t][v]
    __shared__ float4 As[EH];
    __shared__ float2 Gs[EH];

    int b    = blockIdx.x >> 1;
    int half = blockIdx.x & 1;
    int tid  = threadIdx.x;

    for (int i = tid; i < T_DIM * V_DIM; i += NTH) {
        int t = i / V_DIM, v = i - t * V_DIM;
        const float* base = x + (t * B_DIM + b) * (2 * V_DIM);
        xsS[i]                 = base[v];          // x0
        xsS[T_DIM * V_DIM + i] = base[V_DIM + v];  // x1
    }
    if (tid < EH) {
        As[tid] = d_A[half * EH + tid];
        Gs[tid] = d_G[half * EH + tid];
    }
    __syncthreads();

    float4* o4 = reinterpret_cast<float4*>(out);

    #pragma unroll 1
    for (int k = 0; k < 5; k++) {
        int q  = tid + k * NTH;               // local quad in [0,800)
        int p0 = 4 * q;                       // local position in [0,3200)
        int vi[4];
        float w0[4], w1[4], mn[4], rs[4], ga[4], be[4];
        #pragma unroll
        for (int i = 0; i < 4; i++) {
            int pp = p0 + i;
            int e  = pp / V_DIM;              // local channel 0..127
            vi[i]  = pp - e * V_DIM;          // v in [0,25)
            float4 A = As[e];
            float2 G = Gs[e];
            w0[i] = A.x; w1[i] = A.y; mn[i] = A.z; rs[i] = A.w;
            ga[i] = G.x; be[i] = G.y;
        }
        float vs[4] = {0.f, 0.f, 0.f, 0.f};
        float4* op = o4 + b * (E_DIM * V_DIM / 4) + half * QH + q;
        #pragma unroll
        for (int t = 0; t < T_DIM; t++) {
            float4 sp4;
            float* spp = reinterpret_cast<float*>(&sp4);
            #pragma unroll
            for (int i = 0; i < 4; i++) {
                float x0v = xsS[t * V_DIM + vi[i]];
                float x1v = xsS[T_DIM * V_DIM + t * V_DIM + vi[i]];
                float y  = fmaf(x0v, w0[i], x1v * w1[i]);   // conv1x1 (K=2)
                float z  = (y - mn[i]) * rs[i];             // BN normalize
                float yn = fmaf(z, ga[i], be[i]);           // gamma/beta
                float vn = fmaf(yn - vs[i], 0.5f, vs[i]);   // v += (yn - v)/tau
                bool fire = (vn >= 1.0f);
                spp[i] = fire ? 1.0f : 0.0f;                // spike
                vs[i]  = fire ? 0.0f : vn;                  // == vn*(1-sp), bit-exact
            }
            __stcs(op, sp4);                  // streaming store (write-once)
            op += B_DIM * E_DIM * V_DIM / 4;
        }
    }
}

// ---------------------------------------------------------------------------
extern "C" void kernel_launch(void* const* d_in, const int* in_sizes, int n_in,
                              void* d_out, int out_size) {
    const float* x     = (const float*)d_in[0];
    const float* W     = (const float*)d_in[1];
    const float* gamma = (const float*)d_in[2];
    const float* beta  = (const float*)d_in[3];
    float* out = (float*)d_out;

    moments_and_coefs<<<MBLOCKS, MTHREADS>>>(x, W, gamma, beta);
    lif_main<<<B_DIM * 2, NTH>>>(x, out);
}

// round 14
// speedup vs baseline: 1.0811x; 1.0056x over previous
#include <cuda_runtime.h>
#include <math.h>
#include <stdint.h>

#define T_DIM 16
#define B_DIM 512
#define E_DIM 256
#define V_DIM 25
#define NPAIR (T_DIM * B_DIM * V_DIM)   // 204800 (t,b,v) sites
#define MROWS (T_DIM * B_DIM)           // 8192 rows of 50 floats
#define MBLOCKS 128
#define MTHREADS 64

// Scratch (no allocations allowed).
__device__ double d_part[MBLOCKS][5];
__device__ float4 d_A[E_DIM];           // {w0, w1, mean, rstd}
__device__ float2 d_G[E_DIM];           // {gamma, beta}
__device__ unsigned int d_cnt = 0;      // last-block ticket; self-resets each call

// ---- Blackwell packed f32x2 helpers (two independent IEEE-rn fp32 lanes) ----
__device__ __forceinline__ unsigned long long pk2(float lo, float hi) {
    unsigned long long r;
    asm("mov.b64 %0, {%1, %2};" : "=l"(r) : "f"(lo), "f"(hi));
    return r;
}
__device__ __forceinline__ void upk2(float& lo, float& hi, unsigned long long p) {
    asm("mov.b64 {%0, %1}, %2;" : "=f"(lo), "=f"(hi) : "l"(p));
}
__device__ __forceinline__ unsigned long long mul2(unsigned long long a, unsigned long long b) {
    unsigned long long r;
    asm("mul.rn.f32x2 %0, %1, %2;" : "=l"(r) : "l"(a), "l"(b));
    return r;
}
__device__ __forceinline__ unsigned long long fma2(unsigned long long a, unsigned long long b,
                                                   unsigned long long c) {
    unsigned long long r;
    asm("fma.rn.f32x2 %0, %1, %2, %3;" : "=l"(r) : "l"(a), "l"(b), "l"(c));
    return r;
}

// ---------------------------------------------------------------------------
// Kernel 1: UNCHANGED from the passing R12 kernel (numerics frozen).
// ---------------------------------------------------------------------------
__global__ void moments_and_coefs(const float* __restrict__ x,
                                  const float* __restrict__ W,
                                  const float* __restrict__ gamma,
                                  const float* __restrict__ beta) {
    int r = blockIdx.x * MTHREADS + threadIdx.x;   // row id in [0, 8192)
    const float2* row2 = reinterpret_cast<const float2*>(x + r * (2 * V_DIM));

    float f[2 * V_DIM];
    #pragma unroll
    for (int j = 0; j < V_DIM; j++) {              // 25 independent LDG.64
        float2 p = row2[j];
        f[2 * j]     = p.x;
        f[2 * j + 1] = p.y;
    }

    float f0 = 0.f, f1 = 0.f, f2 = 0.f, f3 = 0.f, f4 = 0.f;
    #pragma unroll
    for (int v = 0; v < V_DIM; v++) {
        float x0 = f[v];
        float x1 = f[V_DIM + v];
        f0 += x0;
        f1 += x1;
        f2 = fmaf(x0, x0, f2);
        f3 = fmaf(x1, x1, f3);
        f4 = fmaf(x0, x1, f4);
    }

    double s0 = f0, s1 = f1, s2 = f2, s3 = f3, s4 = f4;
    #pragma unroll
    for (int o = 16; o > 0; o >>= 1) {
        s0 += __shfl_down_sync(0xffffffffu, s0, o);
        s1 += __shfl_down_sync(0xffffffffu, s1, o);
        s2 += __shfl_down_sync(0xffffffffu, s2, o);
        s3 += __shfl_down_sync(0xffffffffu, s3, o);
        s4 += __shfl_down_sync(0xffffffffu, s4, o);
    }
    __shared__ double sh[2][5];
    int w = threadIdx.x >> 5, l = threadIdx.x & 31;
    if (l == 0) { sh[w][0] = s0; sh[w][1] = s1; sh[w][2] = s2; sh[w][3] = s3; sh[w][4] = s4; }
    __syncthreads();
    if (threadIdx.x == 0) {
        d_part[blockIdx.x][0] = sh[0][0] + sh[1][0];
        d_part[blockIdx.x][1] = sh[0][1] + sh[1][1];
        d_part[blockIdx.x][2] = sh[0][2] + sh[1][2];
        d_part[blockIdx.x][3] = sh[0][3] + sh[1][3];
        d_part[blockIdx.x][4] = sh[0][4] + sh[1][4];
        __threadfence();
    }

    __shared__ bool isLast;
    if (threadIdx.x == 0) {
        unsigned int t = atomicAdd(&d_cnt, 1u);
        isLast = (t == (unsigned int)(MBLOCKS - 1));
    }
    __syncthreads();
    if (!isLast) return;

    double p0 = d_part[threadIdx.x][0] + d_part[threadIdx.x + 64][0];
    double p1 = d_part[threadIdx.x][1] + d_part[threadIdx.x + 64][1];
    double p2 = d_part[threadIdx.x][2] + d_part[threadIdx.x + 64][2];
    double p3 = d_part[threadIdx.x][3] + d_part[threadIdx.x + 64][3];
    double p4 = d_part[threadIdx.x][4] + d_part[threadIdx.x + 64][4];
    #pragma unroll
    for (int o = 16; o > 0; o >>= 1) {
        p0 += __shfl_down_sync(0xffffffffu, p0, o);
        p1 += __shfl_down_sync(0xffffffffu, p1, o);
        p2 += __shfl_down_sync(0xffffffffu, p2, o);
        p3 += __shfl_down_sync(0xffffffffu, p3, o);
        p4 += __shfl_down_sync(0xffffffffu, p4, o);
    }
    __shared__ double dsh[2][5];
    if (l == 0) { dsh[w][0] = p0; dsh[w][1] = p1; dsh[w][2] = p2; dsh[w][3] = p3; dsh[w][4] = p4; }
    __syncthreads();
    __shared__ double tot[5];
    if (threadIdx.x < 5) tot[threadIdx.x] = dsh[0][threadIdx.x] + dsh[1][threadIdx.x];
    __syncthreads();

    const double invN = 1.0 / (double)NPAIR;
    double m0  = tot[0] * invN;
    double m1  = tot[1] * invN;
    double s00 = tot[2] * invN;
    double s11 = tot[3] * invN;
    double s01 = tot[4] * invN;

    for (int e = threadIdx.x; e < E_DIM; e += MTHREADS) {
        float w0 = W[2 * e];
        float w1 = W[2 * e + 1];
        double mean = (double)w0 * m0 + (double)w1 * m1;
        double ey2  = (double)w0 * (double)w0 * s00
                    + 2.0 * (double)w0 * (double)w1 * s01
                    + (double)w1 * (double)w1 * s11;
        double var = ey2 - mean * mean;
        if (var < 0.0) var = 0.0;
        float rstd = (float)(1.0 / sqrt(var + 1e-5));
        d_A[e] = make_float4(w0, w1, (float)mean, rstd);
        d_G[e] = make_float2(gamma[e], beta[e]);
    }

    if (threadIdx.x == 0) d_cnt = 0;  // reset for next graph replay
}

// ---------------------------------------------------------------------------
// Kernel 2: fused conv1x1 + BN + LIF scan, f32x2-packed arithmetic.
// Same tiling as R12 (1024 blocks x 160 threads, conflict-free scalar x
// tables). Each scalar op of the frozen chain is replaced by its packed
// twin with IDENTICAL per-lane rn rounding:
//   y  = fma2(x0p, w0p, mul2(x1p, w1p))          == fmaf(x0,w0, x1*w1)
//   z  = mul2(fma2(mnp, -1, y), rsp)             == (y - mn) * rs
//   yn = fma2(z, gap, bep)                       == fmaf(z, ga, be)
//   vn = fma2(fma2(vsp, -1, yn), 0.5, vsp)       == fmaf(yn - vs, 0.5, vs)
// (fma(a,-1,c) = rn(c-a) == FADD(c-a); exact.)  Threshold + reset stay
// scalar on the pair halves (register-pair aliased). Bit-same output.
// ---------------------------------------------------------------------------
#define EH 128                 // channels per block (half of E)
#define QH (EH * V_DIM / 4)    // 800 quads per block
#define NTH 160                // threads per block (5 quads each)

__global__ void __launch_bounds__(NTH, 8)
lif_main(const float* __restrict__ x, float* __restrict__ out) {
    __shared__ float xsS[2 * T_DIM * V_DIM];  // [0:400)=x0[t][v], [400:800)=x1[t][v]
    __shared__ float4 As[EH];
    __shared__ float2 Gs[EH];

    int b    = blockIdx.x >> 1;
    int half = blockIdx.x & 1;
    int tid  = threadIdx.x;

    for (int i = tid; i < T_DIM * V_DIM; i += NTH) {
        int t = i / V_DIM, v = i - t * V_DIM;
        const float* base = x + (t * B_DIM + b) * (2 * V_DIM);
        xsS[i]                 = base[v];          // x0
        xsS[T_DIM * V_DIM + i] = base[V_DIM + v];  // x1
    }
    if (tid < EH) {
        As[tid] = d_A[half * EH + tid];
        Gs[tid] = d_G[half * EH + tid];
    }
    __syncthreads();

    float4* o4 = reinterpret_cast<float4*>(out);

    const unsigned long long NEG1 = pk2(-1.0f, -1.0f);
    const unsigned long long HALF = pk2(0.5f, 0.5f);

    #pragma unroll 1
    for (int k = 0; k < 5; k++) {
        int q  = tid + k * NTH;               // local quad in [0,800)
        int p0 = 4 * q;                       // local position in [0,3200)
        int vi[4];
        float w0s[4], w1s[4], mns[4], rss[4], gas[4], bes[4];
        #pragma unroll
        for (int i = 0; i < 4; i++) {
            int pp = p0 + i;
            int e  = pp / V_DIM;              // local channel 0..127
            vi[i]  = pp - e * V_DIM;          // v in [0,25)
            float4 A = As[e];
            float2 G = Gs[e];
            w0s[i] = A.x; w1s[i] = A.y; mns[i] = A.z; rss[i] = A.w;
            gas[i] = G.x; bes[i] = G.y;
        }
        // packed coefs per pair j (elements 2j, 2j+1)
        unsigned long long w0p[2], w1p[2], mnp[2], rsp[2], gap[2], bep[2];
        #pragma unroll
        for (int j = 0; j < 2; j++) {
            w0p[j] = pk2(w0s[2*j], w0s[2*j+1]);
            w1p[j] = pk2(w1s[2*j], w1s[2*j+1]);
            mnp[j] = pk2(mns[2*j], mns[2*j+1]);
            rsp[j] = pk2(rss[2*j], rss[2*j+1]);
            gap[j] = pk2(gas[2*j], gas[2*j+1]);
            bep[j] = pk2(bes[2*j], bes[2*j+1]);
        }
        float vs[4] = {0.f, 0.f, 0.f, 0.f};
        float4* op = o4 + b * (E_DIM * V_DIM / 4) + half * QH + q;
        #pragma unroll
        for (int t = 0; t < T_DIM; t++) {
            float4 sp4;
            float* spp = reinterpret_cast<float*>(&sp4);
            #pragma unroll
            for (int j = 0; j < 2; j++) {
                float a0 = xsS[t * V_DIM + vi[2*j]];
                float a1 = xsS[t * V_DIM + vi[2*j+1]];
                float c0 = xsS[T_DIM * V_DIM + t * V_DIM + vi[2*j]];
                float c1 = xsS[T_DIM * V_DIM + t * V_DIM + vi[2*j+1]];
                unsigned long long x0p = pk2(a0, a1);
                unsigned long long x1p = pk2(c0, c1);
                unsigned long long vsp = pk2(vs[2*j], vs[2*j+1]);

                unsigned long long y  = fma2(x0p, w0p[j], mul2(x1p, w1p[j]));
                unsigned long long z  = mul2(fma2(mnp[j], NEG1, y), rsp[j]);
                unsigned long long yn = fma2(z, gap[j], bep[j]);
                unsigned long long vn = fma2(fma2(vsp, NEG1, yn), HALF, vsp);

                float v0, v1;
                upk2(v0, v1, vn);
                bool f0 = (v0 >= 1.0f);
                bool f1 = (v1 >= 1.0f);
                spp[2*j]   = f0 ? 1.0f : 0.0f;
                spp[2*j+1] = f1 ? 1.0f : 0.0f;
                vs[2*j]    = f0 ? 0.0f : v0;   // == vn*(1-sp), bit-exact
                vs[2*j+1]  = f1 ? 0.0f : v1;
            }
            __stcs(op, sp4);                  // streaming store (write-once)
            op += B_DIM * E_DIM * V_DIM / 4;
        }
    }
}

// ---------------------------------------------------------------------------
extern "C" void kernel_launch(void* const* d_in, const int* in_sizes, int n_in,
                              void* d_out, int out_size) {
    const float* x     = (const float*)d_in[0];
    const float* W     = (const float*)d_in[1];
    const float* gamma = (const float*)d_in[2];
    const float* beta  = (const float*)d_in[3];
    float* out = (float*)d_out;

    moments_and_coefs<<<MBLOCKS, MTHREADS>>>(x, W, gamma, beta);
    lif_main<<<B_DIM * 2, NTH>>>(x, out);
}

// round 15
// speedup vs baseline: 1.1269x; 1.0423x over previous
#include <cuda_runtime.h>
#include <math.h>

#define T_DIM 16
#define B_DIM 512
#define E_DIM 256
#define V_DIM 25
#define NPAIR (T_DIM * B_DIM * V_DIM)   // 204800 (t,b,v) sites
#define MBLOCKS 128
#define MTHREADS 64

// Scratch (no allocations allowed).
__device__ double d_part[MBLOCKS][5];
__device__ float4 d_A[E_DIM];           // {w0, w1, mean, rstd}
__device__ float2 d_G[E_DIM];           // {gamma, beta}
__device__ unsigned int d_cnt = 0;      // last-block ticket; self-resets each call

// ---------------------------------------------------------------------------
// Kernel 1: UNCHANGED from the passing R12/R14 kernel (numerics frozen).
// ---------------------------------------------------------------------------
__global__ void moments_and_coefs(const float* __restrict__ x,
                                  const float* __restrict__ W,
                                  const float* __restrict__ gamma,
                                  const float* __restrict__ beta) {
    int r = blockIdx.x * MTHREADS + threadIdx.x;   // row id in [0, 8192)
    const float2* row2 = reinterpret_cast<const float2*>(x + r * (2 * V_DIM));

    float f[2 * V_DIM];
    #pragma unroll
    for (int j = 0; j < V_DIM; j++) {              // 25 independent LDG.64
        float2 p = row2[j];
        f[2 * j]     = p.x;
        f[2 * j + 1] = p.y;
    }

    float f0 = 0.f, f1 = 0.f, f2 = 0.f, f3 = 0.f, f4 = 0.f;
    #pragma unroll
    for (int v = 0; v < V_DIM; v++) {
        float x0 = f[v];
        float x1 = f[V_DIM + v];
        f0 += x0;
        f1 += x1;
        f2 = fmaf(x0, x0, f2);
        f3 = fmaf(x1, x1, f3);
        f4 = fmaf(x0, x1, f4);
    }

    double s0 = f0, s1 = f1, s2 = f2, s3 = f3, s4 = f4;
    #pragma unroll
    for (int o = 16; o > 0; o >>= 1) {
        s0 += __shfl_down_sync(0xffffffffu, s0, o);
        s1 += __shfl_down_sync(0xffffffffu, s1, o);
        s2 += __shfl_down_sync(0xffffffffu, s2, o);
        s3 += __shfl_down_sync(0xffffffffu, s3, o);
        s4 += __shfl_down_sync(0xffffffffu, s4, o);
    }
    __shared__ double sh[2][5];
    int w = threadIdx.x >> 5, l = threadIdx.x & 31;
    if (l == 0) { sh[w][0] = s0; sh[w][1] = s1; sh[w][2] = s2; sh[w][3] = s3; sh[w][4] = s4; }
    __syncthreads();
    if (threadIdx.x == 0) {
        d_part[blockIdx.x][0] = sh[0][0] + sh[1][0];
        d_part[blockIdx.x][1] = sh[0][1] + sh[1][1];
        d_part[blockIdx.x][2] = sh[0][2] + sh[1][2];
        d_part[blockIdx.x][3] = sh[0][3] + sh[1][3];
        d_part[blockIdx.x][4] = sh[0][4] + sh[1][4];
        __threadfence();
    }

    __shared__ bool isLast;
    if (threadIdx.x == 0) {
        unsigned int t = atomicAdd(&d_cnt, 1u);
        isLast = (t == (unsigned int)(MBLOCKS - 1));
    }
    __syncthreads();
    if (!isLast) return;

    double p0 = d_part[threadIdx.x][0] + d_part[threadIdx.x + 64][0];
    double p1 = d_part[threadIdx.x][1] + d_part[threadIdx.x + 64][1];
    double p2 = d_part[threadIdx.x][2] + d_part[threadIdx.x + 64][2];
    double p3 = d_part[threadIdx.x][3] + d_part[threadIdx.x + 64][3];
    double p4 = d_part[threadIdx.x][4] + d_part[threadIdx.x + 64][4];
    #pragma unroll
    for (int o = 16; o > 0; o >>= 1) {
        p0 += __shfl_down_sync(0xffffffffu, p0, o);
        p1 += __shfl_down_sync(0xffffffffu, p1, o);
        p2 += __shfl_down_sync(0xffffffffu, p2, o);
        p3 += __shfl_down_sync(0xffffffffu, p3, o);
        p4 += __shfl_down_sync(0xffffffffu, p4, o);
    }
    __shared__ double dsh[2][5];
    if (l == 0) { dsh[w][0] = p0; dsh[w][1] = p1; dsh[w][2] = p2; dsh[w][3] = p3; dsh[w][4] = p4; }
    __syncthreads();
    __shared__ double tot[5];
    if (threadIdx.x < 5) tot[threadIdx.x] = dsh[0][threadIdx.x] + dsh[1][threadIdx.x];
    __syncthreads();

    const double invN = 1.0 / (double)NPAIR;
    double m0  = tot[0] * invN;
    double m1  = tot[1] * invN;
    double s00 = tot[2] * invN;
    double s11 = tot[3] * invN;
    double s01 = tot[4] * invN;

    for (int e = threadIdx.x; e < E_DIM; e += MTHREADS) {
        float w0 = W[2 * e];
        float w1 = W[2 * e + 1];
        double mean = (double)w0 * m0 + (double)w1 * m1;
        double ey2  = (double)w0 * (double)w0 * s00
                    + 2.0 * (double)w0 * (double)w1 * s01
                    + (double)w1 * (double)w1 * s11;
        double var = ey2 - mean * mean;
        if (var < 0.0) var = 0.0;
        float rstd = (float)(1.0 / sqrt(var + 1e-5));
        d_A[e] = make_float4(w0, w1, (float)mean, rstd);
        d_G[e] = make_float2(gamma[e], beta[e]);
    }

    if (threadIdx.x == 0) d_cnt = 0;  // reset for next graph replay
}

// ---------------------------------------------------------------------------
// Kernel 2: fused conv1x1 + BN + LIF scan — R12 scalar chain (frozen math),
// retiled for occupancy: block = (b, 64-channel quarter), 2048 blocks x 128
// threads, __launch_bounds__(128,10) -> 10 resident blocks = 40 warps/SM
// (62.5% occ) with 13.8 blocks/SM of work (no grid starvation, unlike the
// 1024-block layout which capped residency at ~6.9 blocks -> 40% occ).
// Conflict-free scalar x tables; select-based reset (bit-exact). Same output.
// ---------------------------------------------------------------------------
#define EQ 64                  // channels per block (quarter of E)
#define QQ (EQ * V_DIM / 4)    // 400 quads per block
#define NTH 128                // threads per block

__global__ void __launch_bounds__(NTH, 10)
lif_main(const float* __restrict__ x, float* __restrict__ out) {
    __shared__ float xsS[2 * T_DIM * V_DIM];  // [0:400)=x0[t][v], [400:800)=x1[t][v]
    __shared__ float4 As[EQ];
    __shared__ float2 Gs[EQ];

    int b   = blockIdx.x >> 2;
    int qc  = blockIdx.x & 3;          // 64-channel quarter within E=256
    int tid = threadIdx.x;

    for (int i = tid; i < T_DIM * V_DIM; i += NTH) {
        int t = i / V_DIM, v = i - t * V_DIM;
        const float* base = x + (t * B_DIM + b) * (2 * V_DIM);
        xsS[i]                 = base[v];          // x0
        xsS[T_DIM * V_DIM + i] = base[V_DIM + v];  // x1
    }
    if (tid < EQ) {
        As[tid] = d_A[qc * EQ + tid];
        Gs[tid] = d_G[qc * EQ + tid];
    }
    __syncthreads();

    float4* o4 = reinterpret_cast<float4*>(out);

    #pragma unroll 1
    for (int k = 0; k < 4; k++) {
        int q = tid + k * NTH;               // local quad; 400 = 3*128 + 16
        if (q >= QQ) break;
        int p0 = 4 * q;                      // local position in [0,1600)
        int vi[4];
        float w0[4], w1[4], mn[4], rs[4], ga[4], be[4];
        #pragma unroll
        for (int i = 0; i < 4; i++) {
            int pp = p0 + i;
            int e  = pp / V_DIM;             // local channel 0..63
            vi[i]  = pp - e * V_DIM;         // v in [0,25)
            float4 A = As[e];
            float2 G = Gs[e];
            w0[i] = A.x; w1[i] = A.y; mn[i] = A.z; rs[i] = A.w;
            ga[i] = G.x; be[i] = G.y;
        }
        float vs[4] = {0.f, 0.f, 0.f, 0.f};
        float4* op = o4 + b * (E_DIM * V_DIM / 4) + qc * QQ + q;
        #pragma unroll
        for (int t = 0; t < T_DIM; t++) {
            float4 sp4;
            float* spp = reinterpret_cast<float*>(&sp4);
            #pragma unroll
            for (int i = 0; i < 4; i++) {
                float x0v = xsS[t * V_DIM + vi[i]];
                float x1v = xsS[T_DIM * V_DIM + t * V_DIM + vi[i]];
                float y  = fmaf(x0v, w0[i], x1v * w1[i]);   // conv1x1 (K=2)
                float z  = (y - mn[i]) * rs[i];             // BN normalize
                float yn = fmaf(z, ga[i], be[i]);           // gamma/beta
                float vn = fmaf(yn - vs[i], 0.5f, vs[i]);   // v += (yn - v)/tau
                bool fire = (vn >= 1.0f);
                spp[i] = fire ? 1.0f : 0.0f;                // spike
                vs[i]  = fire ? 0.0f : vn;                  // == vn*(1-sp), bit-exact
            }
            __stcs(op, sp4);                 // streaming store (write-once)
            op += B_DIM * E_DIM * V_DIM / 4;
        }
    }
}

// ---------------------------------------------------------------------------
extern "C" void kernel_launch(void* const* d_in, const int* in_sizes, int n_in,
                              void* d_out, int out_size) {
    const float* x     = (const float*)d_in[0];
    const float* W     = (const float*)d_in[1];
    const float* gamma = (const float*)d_in[2];
    const float* beta  = (const float*)d_in[3];
    float* out = (float*)d_out;

    moments_and_coefs<<<MBLOCKS, MTHREADS>>>(x, W, gamma, beta);
    lif_main<<<B_DIM * 4, NTH>>>(x, out);
}

// round 16
// speedup vs baseline: 1.1578x; 1.0274x over previous
#include <cuda_runtime.h>
#include <math.h>

#define T_DIM 16
#define B_DIM 512
#define E_DIM 256
#define V_DIM 25
#define NPAIR (T_DIM * B_DIM * V_DIM)   // 204800 (t,b,v) sites
#define MB 64                           // moment-producer blocks (wave-1 resident)
#define GRID (B_DIM * 4)                // 2048 blocks
#define NTH 128
#define EQ 64                           // channels per block (quarter of E)
#define QQ (EQ * V_DIM / 4)             // 400 quads per block

// Scratch (no allocations allowed).
__device__ double d_part[MB][5];
__device__ float4 d_A[E_DIM];           // {w0, w1, mean, rstd}
__device__ float2 d_G[E_DIM];           // {gamma, beta}
__device__ unsigned int d_cnt  = 0;     // moments ticket
__device__ unsigned int d_flag = 0;     // coefs-ready flag
__device__ unsigned int d_done = 0;     // kernel-exit ticket (resets state)

__device__ __forceinline__ unsigned int ld_volatile_u32(const unsigned int* p) {
    unsigned int v;
    asm volatile("ld.volatile.global.u32 %0, [%1];" : "=r"(v) : "l"(p));
    return v;
}

// ---------------------------------------------------------------------------
// ONE fused kernel.
// Phase A (blocks 0..MB-1 only): 5 moments of x, one (t,b) row per thread,
//   accumulated in the SAME fixed v-order as the frozen R12 kernel, promoted
//   to double for all reduction levels; last-ticket block computes coefs
//   (math unchanged) and releases d_flag.
// Phase B (all blocks): stage x slice (overlaps Phase A), spin on d_flag,
//   load coefs, then the UNCHANGED R15 lif loop.
// ---------------------------------------------------------------------------
__global__ void __launch_bounds__(NTH, 10)
fused_sps(const float* __restrict__ x,
          const float* __restrict__ W,
          const float* __restrict__ gamma,
          const float* __restrict__ beta,
          float* __restrict__ out) {
    __shared__ float xsS[2 * T_DIM * V_DIM];  // [0:400)=x0[t][v], [400:800)=x1[t][v]
    __shared__ float4 As[EQ];
    __shared__ float2 Gs[EQ];

    int b   = blockIdx.x >> 2;
    int qc  = blockIdx.x & 3;          // 64-channel quarter within E=256
    int tid = threadIdx.x;

    // ---------------- Phase A: moments (blocks 0..MB-1) ----------------
    if (blockIdx.x < MB) {
        int r = blockIdx.x * NTH + tid;              // row id in [0, 8192)
        const float* row = x + r * (2 * V_DIM);

        float f0 = 0.f, f1 = 0.f, f2 = 0.f, f3 = 0.f, f4 = 0.f;
        #pragma unroll 5
        for (int v = 0; v < V_DIM; v++) {            // frozen v-order
            float x0 = row[v];
            float x1 = row[V_DIM + v];
            f0 += x0;
            f1 += x1;
            f2 = fmaf(x0, x0, f2);
            f3 = fmaf(x1, x1, f3);
            f4 = fmaf(x0, x1, f4);
        }
        double s0 = f0, s1 = f1, s2 = f2, s3 = f3, s4 = f4;
        #pragma unroll
        for (int o = 16; o > 0; o >>= 1) {
            s0 += __shfl_down_sync(0xffffffffu, s0, o);
            s1 += __shfl_down_sync(0xffffffffu, s1, o);
            s2 += __shfl_down_sync(0xffffffffu, s2, o);
            s3 += __shfl_down_sync(0xffffffffu, s3, o);
            s4 += __shfl_down_sync(0xffffffffu, s4, o);
        }
        __shared__ double msh[4][5];
        int w = tid >> 5, l = tid & 31;
        if (l == 0) { msh[w][0] = s0; msh[w][1] = s1; msh[w][2] = s2; msh[w][3] = s3; msh[w][4] = s4; }
        __syncthreads();
        if (tid == 0) {
            #pragma unroll
            for (int c = 0; c < 5; c++)
                d_part[blockIdx.x][c] = msh[0][c] + msh[1][c] + msh[2][c] + msh[3][c];
            __threadfence();
        }
        __shared__ bool isLast;
        if (tid == 0) {
            unsigned int t = atomicAdd(&d_cnt, 1u);
            isLast = (t == (unsigned int)(MB - 1));
        }
        __syncthreads();
        if (isLast) {
            // combine 64 partials: threads 0..63 hold one each, tree-reduce
            double p0 = 0.0, p1 = 0.0, p2 = 0.0, p3 = 0.0, p4 = 0.0;
            if (tid < MB) {
                p0 = d_part[tid][0]; p1 = d_part[tid][1]; p2 = d_part[tid][2];
                p3 = d_part[tid][3]; p4 = d_part[tid][4];
            }
            #pragma unroll
            for (int o = 16; o > 0; o >>= 1) {
                p0 += __shfl_down_sync(0xffffffffu, p0, o);
                p1 += __shfl_down_sync(0xffffffffu, p1, o);
                p2 += __shfl_down_sync(0xffffffffu, p2, o);
                p3 += __shfl_down_sync(0xffffffffu, p3, o);
                p4 += __shfl_down_sync(0xffffffffu, p4, o);
            }
            __shared__ double dsh[2][5];
            if (l == 0 && w < 2) { dsh[w][0] = p0; dsh[w][1] = p1; dsh[w][2] = p2; dsh[w][3] = p3; dsh[w][4] = p4; }
            __syncthreads();
            __shared__ double tot[5];
            if (tid < 5) tot[tid] = dsh[0][tid] + dsh[1][tid];
            __syncthreads();

            const double invN = 1.0 / (double)NPAIR;
            double m0  = tot[0] * invN;
            double m1  = tot[1] * invN;
            double s00 = tot[2] * invN;
            double s11 = tot[3] * invN;
            double s01 = tot[4] * invN;

            for (int e = tid; e < E_DIM; e += NTH) {
                float w0 = W[2 * e];
                float w1 = W[2 * e + 1];
                double mean = (double)w0 * m0 + (double)w1 * m1;
                double ey2  = (double)w0 * (double)w0 * s00
                            + 2.0 * (double)w0 * (double)w1 * s01
                            + (double)w1 * (double)w1 * s11;
                double var = ey2 - mean * mean;
                if (var < 0.0) var = 0.0;
                float rstd = (float)(1.0 / sqrt(var + 1e-5));
                d_A[e] = make_float4(w0, w1, (float)mean, rstd);
                d_G[e] = make_float2(gamma[e], beta[e]);
            }
            __threadfence();
            __syncthreads();
            if (tid == 0) atomicExch(&d_flag, 1u);   // release coefs
        }
    }

    // ---------------- Phase B: stage x (overlaps Phase A) ----------------
    for (int i = tid; i < T_DIM * V_DIM; i += NTH) {
        int t = i / V_DIM, v = i - t * V_DIM;
        const float* base = x + (t * B_DIM + b) * (2 * V_DIM);
        xsS[i]                 = base[v];          // x0
        xsS[T_DIM * V_DIM + i] = base[V_DIM + v];  // x1
    }

    // wait for coefs
    if (tid == 0) {
        while (ld_volatile_u32(&d_flag) == 0u) __nanosleep(64);
    }
    __syncthreads();
    __threadfence();   // acquire: order coef reads after flag observation

    if (tid < EQ) {
        As[tid] = d_A[qc * EQ + tid];
        Gs[tid] = d_G[qc * EQ + tid];
    }
    __syncthreads();

    // ---------------- lif loop: UNCHANGED from R15 ----------------
    float4* o4 = reinterpret_cast<float4*>(out);

    #pragma unroll 1
    for (int k = 0; k < 4; k++) {
        int q = tid + k * NTH;               // local quad; 400 = 3*128 + 16
        if (q >= QQ) break;
        int p0 = 4 * q;                      // local position in [0,1600)
        int vi[4];
        float w0[4], w1[4], mn[4], rs[4], ga[4], be[4];
        #pragma unroll
        for (int i = 0; i < 4; i++) {
            int pp = p0 + i;
            int e  = pp / V_DIM;             // local channel 0..63
            vi[i]  = pp - e * V_DIM;         // v in [0,25)
            float4 A = As[e];
            float2 G = Gs[e];
            w0[i] = A.x; w1[i] = A.y; mn[i] = A.z; rs[i] = A.w;
            ga[i] = G.x; be[i] = G.y;
        }
        float vs[4] = {0.f, 0.f, 0.f, 0.f};
        float4* op = o4 + b * (E_DIM * V_DIM / 4) + qc * QQ + q;
        #pragma unroll
        for (int t = 0; t < T_DIM; t++) {
            float4 sp4;
            float* spp = reinterpret_cast<float*>(&sp4);
            #pragma unroll
            for (int i = 0; i < 4; i++) {
                float x0v = xsS[t * V_DIM + vi[i]];
                float x1v = xsS[T_DIM * V_DIM + t * V_DIM + vi[i]];
                float y  = fmaf(x0v, w0[i], x1v * w1[i]);   // conv1x1 (K=2)
                float z  = (y - mn[i]) * rs[i];             // BN normalize
                float yn = fmaf(z, ga[i], be[i]);           // gamma/beta
                float vn = fmaf(yn - vs[i], 0.5f, vs[i]);   // v += (yn - v)/tau
                bool fire = (vn >= 1.0f);
                spp[i] = fire ? 1.0f : 0.0f;                // spike
                vs[i]  = fire ? 0.0f : vn;                  // == vn*(1-sp), bit-exact
            }
            __stcs(op, sp4);                 // streaming store (write-once)
            op += B_DIM * E_DIM * V_DIM / 4;
        }
    }

    // ---------------- exit ticket: reset state for next graph replay ----------------
    __syncthreads();
    if (tid == 0) {
        unsigned int t = atomicAdd(&d_done, 1u);
        if (t == (unsigned int)(GRID - 1)) {
            d_flag = 0u;
            d_cnt  = 0u;
            d_done = 0u;
            __threadfence();
        }
    }
}

// ---------------------------------------------------------------------------
extern "C" void kernel_launch(void* const* d_in, const int* in_sizes, int n_in,
                              void* d_out, int out_size) {
    const float* x     = (const float*)d_in[0];
    const float* W     = (const float*)d_in[1];
    const float* gamma = (const float*)d_in[2];
    const float* beta  = (const float*)d_in[3];
    float* out = (float*)d_out;

    fused_sps<<<GRID, NTH>>>(x, W, gamma, beta, out);
}

// round 17
// speedup vs baseline: 1.1585x; 1.0007x over previous
#include <cuda_runtime.h>
#include <math.h>

#define T_DIM 16
#define B_DIM 512
#define E_DIM 256
#define V_DIM 25
#define NPAIR (T_DIM * B_DIM * V_DIM)   // 204800 (t,b,v) sites
#define PB 512                          // producer blocks (all in wave 1)
#define RPB 16                          // rows per producer block (8192/512)
#define GRID (B_DIM * 4)                // 2048 blocks
#define NTH 128
#define EQ 64                           // channels per block (quarter of E)
#define QQ (EQ * V_DIM / 4)             // 400 quads per block

// Scratch (no allocations allowed).
__device__ double d_part[PB][5];
__device__ float4 d_A[E_DIM];           // {w0, w1, mean, rstd}
__device__ float2 d_G[E_DIM];           // {gamma, beta}
__device__ unsigned int d_cnt  = 0;     // moments ticket
__device__ unsigned int d_flag = 0;     // coefs-ready flag
__device__ unsigned int d_done = 0;     // kernel-exit ticket (resets state)

__device__ __forceinline__ unsigned int ld_volatile_u32(const unsigned int* p) {
    unsigned int v;
    asm volatile("ld.volatile.global.u32 %0, [%1];" : "=r"(v) : "l"(p));
    return v;
}

// ---------------------------------------------------------------------------
// ONE fused kernel.
// Phase A (blocks 0..PB-1, all wave-1 resident): moments of x. One (t,b) row
//   per thread (tid<16), 25 LDG.64 (MLP=25), fp32 accumulation in the SAME
//   frozen v-order as R12/R16 -> per-row partials bit-identical. Double for
//   all reduction levels; only the tree shape differs (empirically safe).
//   Last-ticket block combines 512 partials, computes coefs, releases d_flag.
// Phase B (all blocks): stage x slice (overlaps Phase A), spin on d_flag,
//   load coefs, then the UNCHANGED R15/R16 lif loop.
// ---------------------------------------------------------------------------
__global__ void __launch_bounds__(NTH, 10)
fused_sps(const float* __restrict__ x,
          const float* __restrict__ W,
          const float* __restrict__ gamma,
          const float* __restrict__ beta,
          float* __restrict__ out) {
    __shared__ float xsS[2 * T_DIM * V_DIM];  // [0:400)=x0[t][v], [400:800)=x1[t][v]
    __shared__ float4 As[EQ];
    __shared__ float2 Gs[EQ];

    int b   = blockIdx.x >> 2;
    int qc  = blockIdx.x & 3;          // 64-channel quarter within E=256
    int tid = threadIdx.x;

    // ---------------- Phase A: moments (blocks 0..PB-1) ----------------
    if (blockIdx.x < PB) {
        float f0 = 0.f, f1 = 0.f, f2 = 0.f, f3 = 0.f, f4 = 0.f;
        if (tid < RPB) {
            int r = blockIdx.x * RPB + tid;          // row id in [0, 8192)
            const float2* row2 = reinterpret_cast<const float2*>(x + r * (2 * V_DIM));
            float f[2 * V_DIM];
            #pragma unroll
            for (int j = 0; j < V_DIM; j++) {        // 25 independent LDG.64
                float2 p = row2[j];
                f[2 * j]     = p.x;
                f[2 * j + 1] = p.y;
            }
            #pragma unroll
            for (int v = 0; v < V_DIM; v++) {        // frozen v-order
                float x0 = f[v];
                float x1 = f[V_DIM + v];
                f0 += x0;
                f1 += x1;
                f2 = fmaf(x0, x0, f2);
                f3 = fmaf(x1, x1, f3);
                f4 = fmaf(x0, x1, f4);
            }
        }
        if (tid < 32) {                               // warp 0: reduce 16 lanes
            double s0 = f0, s1 = f1, s2 = f2, s3 = f3, s4 = f4;
            #pragma unroll
            for (int o = 8; o > 0; o >>= 1) {
                s0 += __shfl_down_sync(0xffffffffu, s0, o);
                s1 += __shfl_down_sync(0xffffffffu, s1, o);
                s2 += __shfl_down_sync(0xffffffffu, s2, o);
                s3 += __shfl_down_sync(0xffffffffu, s3, o);
                s4 += __shfl_down_sync(0xffffffffu, s4, o);
            }
            if (tid == 0) {
                d_part[blockIdx.x][0] = s0;
                d_part[blockIdx.x][1] = s1;
                d_part[blockIdx.x][2] = s2;
                d_part[blockIdx.x][3] = s3;
                d_part[blockIdx.x][4] = s4;
                __threadfence();
            }
        }
        __shared__ bool isLast;
        if (tid == 0) {
            unsigned int t = atomicAdd(&d_cnt, 1u);
            isLast = (t == (unsigned int)(PB - 1));
        }
        __syncthreads();
        if (isLast) {
            // combine 512 partials: each of 128 threads sums 4, then tree
            double p0 = d_part[tid][0] + d_part[tid+128][0] + d_part[tid+256][0] + d_part[tid+384][0];
            double p1 = d_part[tid][1] + d_part[tid+128][1] + d_part[tid+256][1] + d_part[tid+384][1];
            double p2 = d_part[tid][2] + d_part[tid+128][2] + d_part[tid+256][2] + d_part[tid+384][2];
            double p3 = d_part[tid][3] + d_part[tid+128][3] + d_part[tid+256][3] + d_part[tid+384][3];
            double p4 = d_part[tid][4] + d_part[tid+128][4] + d_part[tid+256][4] + d_part[tid+384][4];
            #pragma unroll
            for (int o = 16; o > 0; o >>= 1) {
                p0 += __shfl_down_sync(0xffffffffu, p0, o);
                p1 += __shfl_down_sync(0xffffffffu, p1, o);
                p2 += __shfl_down_sync(0xffffffffu, p2, o);
                p3 += __shfl_down_sync(0xffffffffu, p3, o);
                p4 += __shfl_down_sync(0xffffffffu, p4, o);
            }
            __shared__ double dsh[4][5];
            int w = tid >> 5, l = tid & 31;
            if (l == 0) { dsh[w][0] = p0; dsh[w][1] = p1; dsh[w][2] = p2; dsh[w][3] = p3; dsh[w][4] = p4; }
            __syncthreads();
            __shared__ double tot[5];
            if (tid < 5) tot[tid] = dsh[0][tid] + dsh[1][tid] + dsh[2][tid] + dsh[3][tid];
            __syncthreads();

            const double invN = 1.0 / (double)NPAIR;
            double m0  = tot[0] * invN;
            double m1  = tot[1] * invN;
            double s00 = tot[2] * invN;
            double s11 = tot[3] * invN;
            double s01 = tot[4] * invN;

            for (int e = tid; e < E_DIM; e += NTH) {
                float w0 = W[2 * e];
                float w1 = W[2 * e + 1];
                double mean = (double)w0 * m0 + (double)w1 * m1;
                double ey2  = (double)w0 * (double)w0 * s00
                            + 2.0 * (double)w0 * (double)w1 * s01
                            + (double)w1 * (double)w1 * s11;
                double var = ey2 - mean * mean;
                if (var < 0.0) var = 0.0;
                float rstd = (float)(1.0 / sqrt(var + 1e-5));
                d_A[e] = make_float4(w0, w1, (float)mean, rstd);
                d_G[e] = make_float2(gamma[e], beta[e]);
            }
            __threadfence();
            __syncthreads();
            if (tid == 0) atomicExch(&d_flag, 1u);   // release coefs
        }
    }

    // ---------------- Phase B: stage x (overlaps Phase A) ----------------
    for (int i = tid; i < T_DIM * V_DIM; i += NTH) {
        int t = i / V_DIM, v = i - t * V_DIM;
        const float* base = x + (t * B_DIM + b) * (2 * V_DIM);
        xsS[i]                 = base[v];          // x0
        xsS[T_DIM * V_DIM + i] = base[V_DIM + v];  // x1
    }

    // wait for coefs
    if (tid == 0) {
        while (ld_volatile_u32(&d_flag) == 0u) __nanosleep(64);
    }
    __syncthreads();
    __threadfence();   // acquire: order coef reads after flag observation

    if (tid < EQ) {
        As[tid] = d_A[qc * EQ + tid];
        Gs[tid] = d_G[qc * EQ + tid];
    }
    __syncthreads();

    // ---------------- lif loop: UNCHANGED ----------------
    float4* o4 = reinterpret_cast<float4*>(out);

    #pragma unroll 1
    for (int k = 0; k < 4; k++) {
        int q = tid + k * NTH;               // local quad; 400 = 3*128 + 16
        if (q >= QQ) break;
        int p0 = 4 * q;                      // local position in [0,1600)
        int vi[4];
        float w0[4], w1[4], mn[4], rs[4], ga[4], be[4];
        #pragma unroll
        for (int i = 0; i < 4; i++) {
            int pp = p0 + i;
            int e  = pp / V_DIM;             // local channel 0..63
            vi[i]  = pp - e * V_DIM;         // v in [0,25)
            float4 A = As[e];
            float2 G = Gs[e];
            w0[i] = A.x; w1[i] = A.y; mn[i] = A.z; rs[i] = A.w;
            ga[i] = G.x; be[i] = G.y;
        }
        float vs[4] = {0.f, 0.f, 0.f, 0.f};
        float4* op = o4 + b * (E_DIM * V_DIM / 4) + qc * QQ + q;
        #pragma unroll
        for (int t = 0; t < T_DIM; t++) {
            float4 sp4;
            float* spp = reinterpret_cast<float*>(&sp4);
            #pragma unroll
            for (int i = 0; i < 4; i++) {
                float x0v = xsS[t * V_DIM + vi[i]];
                float x1v = xsS[T_DIM * V_DIM + t * V_DIM + vi[i]];
                float y  = fmaf(x0v, w0[i], x1v * w1[i]);   // conv1x1 (K=2)
                float z  = (y - mn[i]) * rs[i];             // BN normalize
                float yn = fmaf(z, ga[i], be[i]);           // gamma/beta
                float vn = fmaf(yn - vs[i], 0.5f, vs[i]);   // v += (yn - v)/tau
                bool fire = (vn >= 1.0f);
                spp[i] = fire ? 1.0f : 0.0f;                // spike
                vs[i]  = fire ? 0.0f : vn;                  // == vn*(1-sp), bit-exact
            }
            __stcs(op, sp4);                 // streaming store (write-once)
            op += B_DIM * E_DIM * V_DIM / 4;
        }
    }

    // ---------------- exit ticket: reset state for next graph replay ----------------
    __syncthreads();
    if (tid == 0) {
        unsigned int t = atomicAdd(&d_done, 1u);
        if (t == (unsigned int)(GRID - 1)) {
            d_flag = 0u;
            d_cnt  = 0u;
            d_done = 0u;
            __threadfence();
        }
    }
}

// ---------------------------------------------------------------------------
extern "C" void kernel_launch(void* const* d_in, const int* in_sizes, int n_in,
                              void* d_out, int out_size) {
    const float* x     = (const float*)d_in[0];
    const float* W     = (const float*)d_in[1];
    const float* gamma = (const float*)d_in[2];
    const float* beta  = (const float*)d_in[3];
    float* out = (float*)d_out;

    fused_sps<<<GRID, NTH>>>(x, W, gamma, beta, out);
}